// round 6
// baseline (speedup 1.0000x reference)
#include <cuda_runtime.h>
#include <math.h>

typedef unsigned long long u64;

#define SEQ   2048
#define DM    1024
#define NH    16
#define DKK   64
#define BATCH 2
#define MT    (BATCH*SEQ)   // 4096 rows

// Scratch (device globals: allocation-free rule)
__device__ float g_q[BATCH*NH*SEQ*DKK];     // [b,h,s,d]
__device__ float g_k[BATCH*NH*SEQ*DKK];     // [b,h,s,d]
__device__ float g_v[BATCH*NH*SEQ*DKK];     // [b,h,s,d]
__device__ float g_attn[MT*DM];             // [m, h*64+d] row-major

// ---- packed fp32x2 helpers (B300 double-rate fp32) ----
__device__ __forceinline__ u64 pack2(float x, float y) {
    u64 r; asm("mov.b64 %0, {%1, %2};" : "=l"(r) : "f"(x), "f"(y)); return r;
}
__device__ __forceinline__ float2 unpack2(u64 v) {
    float2 f; asm("mov.b64 {%0, %1}, %2;" : "=f"(f.x), "=f"(f.y) : "l"(v)); return f;
}
__device__ __forceinline__ void fma2(u64& d, u64 a, u64 b) {
    asm("fma.rn.f32x2 %0, %1, %2, %0;" : "+l"(d) : "l"(a), "l"(b));
}
__device__ __forceinline__ void mul2(u64& d, u64 a) {
    asm("mul.rn.f32x2 %0, %0, %1;" : "+l"(d) : "l"(a));
}

union F4U2 { float4 f4; u64 u2[2]; };

// ============================================================
// 128x128x8 SGEMM tile, C[m,n] = sum_k A[m,k]*B[n,k]
// 256 threads, 8x8 per thread, inner products via fma.rn.f32x2
// ============================================================
__device__ __forceinline__ void gemm128(const float* __restrict__ A,
                                        const float* __restrict__ B,
                                        u64 acc[8][4])
{
    __shared__ float As[8][128];
    __shared__ float Bs[8][128];
    const int tid  = threadIdx.x;
    const int bm   = blockIdx.y * 128;
    const int bn   = blockIdx.x * 128;
    const int rowL = tid >> 1;          // 0..127
    const int colL = (tid & 1) * 4;     // 0 or 4
    const float* Ap = A + (size_t)(bm + rowL) * DM + colL;
    const float* Bp = B + (size_t)(bn + rowL) * DM + colL;
    const int tr = (tid >> 4) * 8;      // row tile offset
    const int tc = (tid & 15) * 8;      // col tile offset

    for (int k0 = 0; k0 < DM; k0 += 8) {
        float4 a4 = *(const float4*)(Ap + k0);
        float4 b4 = *(const float4*)(Bp + k0);
        __syncthreads();   // previous compute done before overwrite
        As[colL+0][rowL] = a4.x; As[colL+1][rowL] = a4.y;
        As[colL+2][rowL] = a4.z; As[colL+3][rowL] = a4.w;
        Bs[colL+0][rowL] = b4.x; Bs[colL+1][rowL] = b4.y;
        Bs[colL+2][rowL] = b4.z; Bs[colL+3][rowL] = b4.w;
        __syncthreads();
        #pragma unroll
        for (int k = 0; k < 8; k++) {
            float4 a0 = *(const float4*)&As[k][tr];
            float4 a1 = *(const float4*)&As[k][tr + 4];
            F4U2 b0, b1;
            b0.f4 = *(const float4*)&Bs[k][tc];
            b1.f4 = *(const float4*)&Bs[k][tc + 4];
            u64 rb0 = b0.u2[0], rb1 = b0.u2[1], rb2 = b1.u2[0], rb3 = b1.u2[1];
            float ra[8] = {a0.x, a0.y, a0.z, a0.w, a1.x, a1.y, a1.z, a1.w};
            #pragma unroll
            for (int i = 0; i < 8; i++) {
                u64 ai = pack2(ra[i], ra[i]);
                fma2(acc[i][0], ai, rb0);
                fma2(acc[i][1], ai, rb1);
                fma2(acc[i][2], ai, rb2);
                fma2(acc[i][3], ai, rb3);
            }
        }
    }
}

// ============================================================
// QKV projection + RoPE.  z: 0=Q(rope), 1=K(rope), 2=V
// Writes [b,h,s,d] layout for attention.
// ============================================================
__global__ __launch_bounds__(256, 2)
void qkv_kernel(const float* __restrict__ x, const int* __restrict__ posns,
                const float* __restrict__ wq, const float* __restrict__ wk,
                const float* __restrict__ wv)
{
    const int z = blockIdx.z;
    const float* B = (z == 0) ? wq : (z == 1) ? wk : wv;
    u64 acc[8][4] = {};
    gemm128(x, B, acc);

    float* dst = (z == 0) ? g_q : (z == 1) ? g_k : g_v;
    const int tid = threadIdx.x;
    const int bm  = blockIdx.y * 128;
    const int bn  = blockIdx.x * 128;
    const int tr  = (tid >> 4) * 8;
    const int tc  = (tid & 15) * 8;
    const int cn0 = bn + tc;            // 8 consecutive cols, within one head
    const int h   = cn0 >> 6;
    const int d0  = cn0 & 63;

    float inv[4];
    if (z < 2) {
        #pragma unroll
        for (int t2 = 0; t2 < 4; t2++)
            inv[t2] = 1.0f / powf(10000.0f, (float)(d0 + 2*t2) * (1.0f/64.0f));
    }

    #pragma unroll
    for (int i = 0; i < 8; i++) {
        int rm = bm + tr + i;
        int bb = rm >> 11;
        int s  = rm & 2047;
        float2 c0 = unpack2(acc[i][0]);
        float2 c1 = unpack2(acc[i][1]);
        float2 c2 = unpack2(acc[i][2]);
        float2 c3 = unpack2(acc[i][3]);
        float y[8] = {c0.x, c0.y, c1.x, c1.y, c2.x, c2.y, c3.x, c3.y};
        if (z < 2) {
            float fp = (float)posns[s];
            #pragma unroll
            for (int t2 = 0; t2 < 4; t2++) {
                float ang = fp * inv[t2];
                float sn, cs;
                sincosf(ang, &sn, &cs);
                float x0 = y[2*t2], x1 = y[2*t2 + 1];
                y[2*t2]     = x0 * cs - x1 * sn;
                y[2*t2 + 1] = x0 * sn + x1 * cs;
            }
        }
        float* drow = dst + (((size_t)(bb * NH + h) * SEQ + s) * DKK + d0);
        *(float4*)&drow[0] = make_float4(y[0], y[1], y[2], y[3]);
        *(float4*)&drow[4] = make_float4(y[4], y[5], y[6], y[7]);
    }
}

// ============================================================
// Causal flash attention, fp32, 1 thread = 1 query row.
// Block: 128 threads = 128 queries of one (b,h). K/V tiles (64x64) in smem.
// q pre-scaled by 1/sqrt(dk). Online softmax with rare-rescale branch.
// ============================================================
__global__ __launch_bounds__(128)
void attn_kernel()
{
    const int t  = threadIdx.x;
    const int q0 = blockIdx.x * 128;
    const int h  = blockIdx.y;
    const int b  = blockIdx.z;
    const int qi = q0 + t;
    const size_t base = (size_t)(b * NH + h) * SEQ * DKK;

    // load & pre-scale query (packed pairs)
    u64 q2[32];
    {
        const float* Qp = g_q + base + (size_t)qi * DKK;
        #pragma unroll
        for (int i = 0; i < 16; i++) {
            float4 v = *(const float4*)(Qp + i * 4);
            q2[2*i]     = pack2(v.x * 0.125f, v.y * 0.125f);
            q2[2*i + 1] = pack2(v.z * 0.125f, v.w * 0.125f);
        }
    }
    u64 o2[32] = {};
    float mrow = -1e30f;
    float l = 0.0f;

    __shared__ float Ks[64 * 64];
    __shared__ float Vs[64 * 64];

    const int kend = q0 + 128;   // exclusive bound on keys needed by this block
    for (int kt = 0; kt < kend; kt += 64) {
        const float* Kg = g_k + base + (size_t)kt * DKK;
        const float* Vg = g_v + base + (size_t)kt * DKK;
        __syncthreads();
        #pragma unroll
        for (int r = 0; r < 8; r++) {
            int idx = (t + r * 128) * 4;   // float offset 0..4092
            *(float4*)&Ks[idx] = *(const float4*)&Kg[idx];
            *(float4*)&Vs[idx] = *(const float4*)&Vg[idx];
        }
        __syncthreads();

        int jmax = qi - kt + 1;
        if (jmax > 64) jmax = 64;
        for (int j = 0; j < jmax; j++) {
            // s = q . k_j   (4 packed accumulator chains)
            const float4* Kf4 = (const float4*)(Ks + j * 64);
            u64 accs[4] = {0, 0, 0, 0};
            #pragma unroll
            for (int i2 = 0; i2 < 16; i2++) {
                F4U2 kk; kk.f4 = Kf4[i2];
                fma2(accs[(2*i2)     & 3], q2[2*i2],     kk.u2[0]);
                fma2(accs[(2*i2 + 1) & 3], q2[2*i2 + 1], kk.u2[1]);
            }
            float2 fa = unpack2(accs[0]), fb = unpack2(accs[1]);
            float2 fc = unpack2(accs[2]), fd = unpack2(accs[3]);
            float s = ((fa.x + fa.y) + (fb.x + fb.y)) +
                      ((fc.x + fc.y) + (fd.x + fd.y));

            if (s > mrow) {           // rare after warmup
                float r = __expf(mrow - s);
                u64 r2 = pack2(r, r);
                #pragma unroll
                for (int i = 0; i < 32; i++) mul2(o2[i], r2);
                l *= r;
                mrow = s;
            }
            float p = __expf(s - mrow);
            l += p;
            u64 p2 = pack2(p, p);
            const float4* Vf4 = (const float4*)(Vs + j * 64);
            #pragma unroll
            for (int i2 = 0; i2 < 16; i2++) {
                F4U2 vv; vv.f4 = Vf4[i2];
                fma2(o2[2*i2],     p2, vv.u2[0]);
                fma2(o2[2*i2 + 1], p2, vv.u2[1]);
            }
        }
    }

    float invl = 1.0f / l;
    float* dst = g_attn + ((size_t)(b * SEQ + qi) * NH + h) * DKK;
    #pragma unroll
    for (int i = 0; i < 16; i++) {
        float2 a = unpack2(o2[2*i]);
        float2 c = unpack2(o2[2*i + 1]);
        *(float4*)&dst[i * 4] =
            make_float4(a.x * invl, a.y * invl, c.x * invl, c.y * invl);
    }
}

// ============================================================
// Output projection: d_out = g_attn @ w_o^T
// ============================================================
__global__ __launch_bounds__(256, 2)
void out_kernel(const float* __restrict__ wo, float* __restrict__ outp)
{
    u64 acc[8][4] = {};
    gemm128(g_attn, wo, acc);

    const int tid = threadIdx.x;
    const int bm  = blockIdx.y * 128;
    const int cn0 = blockIdx.x * 128 + (tid & 15) * 8;
    const int tr  = (tid >> 4) * 8;
    #pragma unroll
    for (int i = 0; i < 8; i++) {
        int rm = bm + tr + i;
        float2 c0 = unpack2(acc[i][0]);
        float2 c1 = unpack2(acc[i][1]);
        float2 c2 = unpack2(acc[i][2]);
        float2 c3 = unpack2(acc[i][3]);
        float* drow = outp + (size_t)rm * DM + cn0;
        *(float4*)&drow[0] = make_float4(c0.x, c0.y, c1.x, c1.y);
        *(float4*)&drow[4] = make_float4(c2.x, c2.y, c3.x, c3.y);
    }
}

extern "C" void kernel_launch(void* const* d_in, const int* in_sizes, int n_in,
                              void* d_out, int out_size)
{
    (void)in_sizes; (void)n_in; (void)out_size;
    const float* x    = (const float*)d_in[0];
    const int*   pos  = (const int*)  d_in[1];
    const float* wq   = (const float*)d_in[2];
    const float* wk   = (const float*)d_in[3];
    const float* wv   = (const float*)d_in[4];
    const float* wo   = (const float*)d_in[5];
    float*       outp = (float*)d_out;

    dim3 g1(DM / 128, MT / 128, 3);          // (8, 32, 3)
    qkv_kernel<<<g1, 256>>>(x, pos, wq, wk, wv);

    dim3 g2(SEQ / 128, NH, BATCH);           // (16, 16, 2)
    attn_kernel<<<g2, 128>>>();

    dim3 g3(DM / 128, MT / 128, 1);          // (8, 32)
    out_kernel<<<g3, 256>>>(wo, outp);
}

// round 7
// speedup vs baseline: 1.0041x; 1.0041x over previous
#include <cuda_runtime.h>
#include <math.h>

typedef unsigned long long u64;

#define SEQ   2048
#define DM    1024
#define NH    16
#define DKK   64
#define BATCH 2
#define MT    (BATCH*SEQ)   // 4096 rows

// Scratch (device globals: allocation-free rule)
__device__ float g_q[BATCH*NH*SEQ*DKK];     // [b,h,s,d]
__device__ float g_k[BATCH*NH*SEQ*DKK];     // [b,h,s,d]
__device__ float g_v[BATCH*NH*SEQ*DKK];     // [b,h,s,d]
__device__ float g_attn[MT*DM];             // [m, h*64+d] row-major

// ---- packed fp32x2 helpers (B300 double-rate fp32) ----
__device__ __forceinline__ u64 pack2(float x, float y) {
    u64 r; asm("mov.b64 %0, {%1, %2};" : "=l"(r) : "f"(x), "f"(y)); return r;
}
__device__ __forceinline__ float2 unpack2(u64 v) {
    float2 f; asm("mov.b64 {%0, %1}, %2;" : "=f"(f.x), "=f"(f.y) : "l"(v)); return f;
}
__device__ __forceinline__ void fma2(u64& d, u64 a, u64 b) {
    asm("fma.rn.f32x2 %0, %1, %2, %0;" : "+l"(d) : "l"(a), "l"(b));
}
__device__ __forceinline__ void mul2(u64& d, u64 a) {
    asm("mul.rn.f32x2 %0, %0, %1;" : "+l"(d) : "l"(a));
}

union F4U2 { float4 f4; u64 u2[2]; };

// ============================================================
// 128x128x8 SGEMM tile, C[m,n] = sum_k A[m,k]*B[n,k]
// 256 threads, 8x8 per thread, inner products via fma.rn.f32x2
// ============================================================
__device__ __forceinline__ void gemm128(const float* __restrict__ A,
                                        const float* __restrict__ B,
                                        u64 acc[8][4])
{
    __shared__ float As[8][128];
    __shared__ float Bs[8][128];
    const int tid  = threadIdx.x;
    const int bm   = blockIdx.y * 128;
    const int bn   = blockIdx.x * 128;
    const int rowL = tid >> 1;          // 0..127
    const int colL = (tid & 1) * 4;     // 0 or 4
    const float* Ap = A + (size_t)(bm + rowL) * DM + colL;
    const float* Bp = B + (size_t)(bn + rowL) * DM + colL;
    const int tr = (tid >> 4) * 8;      // row tile offset
    const int tc = (tid & 15) * 8;      // col tile offset

    for (int k0 = 0; k0 < DM; k0 += 8) {
        float4 a4 = *(const float4*)(Ap + k0);
        float4 b4 = *(const float4*)(Bp + k0);
        __syncthreads();   // previous compute done before overwrite
        As[colL+0][rowL] = a4.x; As[colL+1][rowL] = a4.y;
        As[colL+2][rowL] = a4.z; As[colL+3][rowL] = a4.w;
        Bs[colL+0][rowL] = b4.x; Bs[colL+1][rowL] = b4.y;
        Bs[colL+2][rowL] = b4.z; Bs[colL+3][rowL] = b4.w;
        __syncthreads();
        #pragma unroll
        for (int k = 0; k < 8; k++) {
            float4 a0 = *(const float4*)&As[k][tr];
            float4 a1 = *(const float4*)&As[k][tr + 4];
            F4U2 b0, b1;
            b0.f4 = *(const float4*)&Bs[k][tc];
            b1.f4 = *(const float4*)&Bs[k][tc + 4];
            u64 rb0 = b0.u2[0], rb1 = b0.u2[1], rb2 = b1.u2[0], rb3 = b1.u2[1];
            float ra[8] = {a0.x, a0.y, a0.z, a0.w, a1.x, a1.y, a1.z, a1.w};
            #pragma unroll
            for (int i = 0; i < 8; i++) {
                u64 ai = pack2(ra[i], ra[i]);
                fma2(acc[i][0], ai, rb0);
                fma2(acc[i][1], ai, rb1);
                fma2(acc[i][2], ai, rb2);
                fma2(acc[i][3], ai, rb3);
            }
        }
    }
}

// ============================================================
// QKV projection + RoPE.  z: 0=Q(rope), 1=K(rope), 2=V
// Writes [b,h,s,d] layout for attention.
// ============================================================
__global__ __launch_bounds__(256, 2)
void qkv_kernel(const float* __restrict__ x, const int* __restrict__ posns,
                const float* __restrict__ wq, const float* __restrict__ wk,
                const float* __restrict__ wv)
{
    const int z = blockIdx.z;
    const float* B = (z == 0) ? wq : (z == 1) ? wk : wv;
    u64 acc[8][4] = {};
    gemm128(x, B, acc);

    float* dst = (z == 0) ? g_q : (z == 1) ? g_k : g_v;
    const int tid = threadIdx.x;
    const int bm  = blockIdx.y * 128;
    const int bn  = blockIdx.x * 128;
    const int tr  = (tid >> 4) * 8;
    const int tc  = (tid & 15) * 8;
    const int cn0 = bn + tc;            // 8 consecutive cols, within one head
    const int h   = cn0 >> 6;
    const int d0  = cn0 & 63;

    float inv[4];
    if (z < 2) {
        #pragma unroll
        for (int t2 = 0; t2 < 4; t2++)
            inv[t2] = 1.0f / powf(10000.0f, (float)(d0 + 2*t2) * (1.0f/64.0f));
    }

    #pragma unroll
    for (int i = 0; i < 8; i++) {
        int rm = bm + tr + i;
        int bb = rm >> 11;
        int s  = rm & 2047;
        float2 c0 = unpack2(acc[i][0]);
        float2 c1 = unpack2(acc[i][1]);
        float2 c2 = unpack2(acc[i][2]);
        float2 c3 = unpack2(acc[i][3]);
        float y[8] = {c0.x, c0.y, c1.x, c1.y, c2.x, c2.y, c3.x, c3.y};
        if (z < 2) {
            float fp = (float)posns[s];
            #pragma unroll
            for (int t2 = 0; t2 < 4; t2++) {
                float ang = fp * inv[t2];
                float sn, cs;
                sincosf(ang, &sn, &cs);
                float x0 = y[2*t2], x1 = y[2*t2 + 1];
                y[2*t2]     = x0 * cs - x1 * sn;
                y[2*t2 + 1] = x0 * sn + x1 * cs;
            }
        }
        float* drow = dst + (((size_t)(bb * NH + h) * SEQ + s) * DKK + d0);
        *(float4*)&drow[0] = make_float4(y[0], y[1], y[2], y[3]);
        *(float4*)&drow[4] = make_float4(y[4], y[5], y[6], y[7]);
    }
}

// ============================================================
// Causal flash attention, fp32, 1 thread = 1 query row.
// Block: 128 threads = 128 queries of one (b,h). K/V tiles (64x64) in smem.
// q pre-scaled by 1/sqrt(dk). Online softmax with rare-rescale branch.
// ============================================================
__global__ __launch_bounds__(128)
void attn_kernel()
{
    const int t  = threadIdx.x;
    const int q0 = blockIdx.x * 128;
    const int h  = blockIdx.y;
    const int b  = blockIdx.z;
    const int qi = q0 + t;
    const size_t base = (size_t)(b * NH + h) * SEQ * DKK;

    // load & pre-scale query (packed pairs)
    u64 q2[32];
    {
        const float* Qp = g_q + base + (size_t)qi * DKK;
        #pragma unroll
        for (int i = 0; i < 16; i++) {
            float4 v = *(const float4*)(Qp + i * 4);
            q2[2*i]     = pack2(v.x * 0.125f, v.y * 0.125f);
            q2[2*i + 1] = pack2(v.z * 0.125f, v.w * 0.125f);
        }
    }
    u64 o2[32] = {};
    float mrow = -1e30f;
    float l = 0.0f;

    __shared__ float Ks[64 * 64];
    __shared__ float Vs[64 * 64];

    const int kend = q0 + 128;   // exclusive bound on keys needed by this block
    for (int kt = 0; kt < kend; kt += 64) {
        const float* Kg = g_k + base + (size_t)kt * DKK;
        const float* Vg = g_v + base + (size_t)kt * DKK;
        __syncthreads();
        #pragma unroll
        for (int r = 0; r < 8; r++) {
            int idx = (t + r * 128) * 4;   // float offset 0..4092
            *(float4*)&Ks[idx] = *(const float4*)&Kg[idx];
            *(float4*)&Vs[idx] = *(const float4*)&Vg[idx];
        }
        __syncthreads();

        int jmax = qi - kt + 1;
        if (jmax > 64) jmax = 64;
        for (int j = 0; j < jmax; j++) {
            // s = q . k_j   (4 packed accumulator chains)
            const float4* Kf4 = (const float4*)(Ks + j * 64);
            u64 accs[4] = {0, 0, 0, 0};
            #pragma unroll
            for (int i2 = 0; i2 < 16; i2++) {
                F4U2 kk; kk.f4 = Kf4[i2];
                fma2(accs[(2*i2)     & 3], q2[2*i2],     kk.u2[0]);
                fma2(accs[(2*i2 + 1) & 3], q2[2*i2 + 1], kk.u2[1]);
            }
            float2 fa = unpack2(accs[0]), fb = unpack2(accs[1]);
            float2 fc = unpack2(accs[2]), fd = unpack2(accs[3]);
            float s = ((fa.x + fa.y) + (fb.x + fb.y)) +
                      ((fc.x + fc.y) + (fd.x + fd.y));

            if (s > mrow) {           // rare after warmup
                float r = __expf(mrow - s);
                u64 r2 = pack2(r, r);
                #pragma unroll
                for (int i = 0; i < 32; i++) mul2(o2[i], r2);
                l *= r;
                mrow = s;
            }
            float p = __expf(s - mrow);
            l += p;
            u64 p2 = pack2(p, p);
            const float4* Vf4 = (const float4*)(Vs + j * 64);
            #pragma unroll
            for (int i2 = 0; i2 < 16; i2++) {
                F4U2 vv; vv.f4 = Vf4[i2];
                fma2(o2[2*i2],     p2, vv.u2[0]);
                fma2(o2[2*i2 + 1], p2, vv.u2[1]);
            }
        }
    }

    float invl = 1.0f / l;
    float* dst = g_attn + ((size_t)(b * SEQ + qi) * NH + h) * DKK;
    #pragma unroll
    for (int i = 0; i < 16; i++) {
        float2 a = unpack2(o2[2*i]);
        float2 c = unpack2(o2[2*i + 1]);
        *(float4*)&dst[i * 4] =
            make_float4(a.x * invl, a.y * invl, c.x * invl, c.y * invl);
    }
}

// ============================================================
// Output projection: d_out = g_attn @ w_o^T
// ============================================================
__global__ __launch_bounds__(256, 2)
void out_kernel(const float* __restrict__ wo, float* __restrict__ outp)
{
    u64 acc[8][4] = {};
    gemm128(g_attn, wo, acc);

    const int tid = threadIdx.x;
    const int bm  = blockIdx.y * 128;
    const int cn0 = blockIdx.x * 128 + (tid & 15) * 8;
    const int tr  = (tid >> 4) * 8;
    #pragma unroll
    for (int i = 0; i < 8; i++) {
        int rm = bm + tr + i;
        float2 c0 = unpack2(acc[i][0]);
        float2 c1 = unpack2(acc[i][1]);
        float2 c2 = unpack2(acc[i][2]);
        float2 c3 = unpack2(acc[i][3]);
        float* drow = outp + (size_t)rm * DM + cn0;
        *(float4*)&drow[0] = make_float4(c0.x, c0.y, c1.x, c1.y);
        *(float4*)&drow[4] = make_float4(c2.x, c2.y, c3.x, c3.y);
    }
}

extern "C" void kernel_launch(void* const* d_in, const int* in_sizes, int n_in,
                              void* d_out, int out_size)
{
    (void)in_sizes; (void)n_in; (void)out_size;
    const float* x    = (const float*)d_in[0];
    const int*   pos  = (const int*)  d_in[1];
    const float* wq   = (const float*)d_in[2];
    const float* wk   = (const float*)d_in[3];
    const float* wv   = (const float*)d_in[4];
    const float* wo   = (const float*)d_in[5];
    float*       outp = (float*)d_out;

    dim3 g1(DM / 128, MT / 128, 3);          // (8, 32, 3)
    qkv_kernel<<<g1, 256>>>(x, pos, wq, wk, wv);

    dim3 g2(SEQ / 128, NH, BATCH);           // (16, 16, 2)
    attn_kernel<<<g2, 128>>>();

    dim3 g3(DM / 128, MT / 128, 1);          // (8, 32)
    out_kernel<<<g3, 256>>>(wo, outp);
}

// round 8
// speedup vs baseline: 1.0146x; 1.0104x over previous
#include <cuda_runtime.h>
#include <math.h>

typedef unsigned long long u64;

#define SEQ   2048
#define DM    1024
#define NH    16
#define DKK   64
#define BATCH 2
#define MT    (BATCH*SEQ)   // 4096 rows

// Scratch (device globals: allocation-free rule)
__device__ float g_q[BATCH*NH*SEQ*DKK];     // [b,h,s,d]
__device__ float g_k[BATCH*NH*SEQ*DKK];     // [b,h,s,d]
__device__ float g_v[BATCH*NH*SEQ*DKK];     // [b,h,s,d]
__device__ float g_attn[MT*DM];             // [m, h*64+d] row-major

// ---- packed fp32x2 helpers (B300 double-rate fp32) ----
__device__ __forceinline__ u64 pack2(float x, float y) {
    u64 r; asm("mov.b64 %0, {%1, %2};" : "=l"(r) : "f"(x), "f"(y)); return r;
}
__device__ __forceinline__ float2 unpack2(u64 v) {
    float2 f; asm("mov.b64 {%0, %1}, %2;" : "=f"(f.x), "=f"(f.y) : "l"(v)); return f;
}
__device__ __forceinline__ void fma2(u64& d, u64 a, u64 b) {
    asm("fma.rn.f32x2 %0, %1, %2, %0;" : "+l"(d) : "l"(a), "l"(b));
}
__device__ __forceinline__ void mul2(u64& d, u64 a) {
    asm("mul.rn.f32x2 %0, %0, %1;" : "+l"(d) : "l"(a));
}

union F4U2 { float4 f4; u64 u2[2]; };

// ============================================================
// 128x128x8 SGEMM tile, C[m,n] = sum_k A[m,k]*B[n,k]
// 256 threads, 8x8 per thread, inner products via fma.rn.f32x2
// ============================================================
__device__ __forceinline__ void gemm128(const float* __restrict__ A,
                                        const float* __restrict__ B,
                                        u64 acc[8][4])
{
    __shared__ float As[8][128];
    __shared__ float Bs[8][128];
    const int tid  = threadIdx.x;
    const int bm   = blockIdx.y * 128;
    const int bn   = blockIdx.x * 128;
    const int rowL = tid >> 1;          // 0..127
    const int colL = (tid & 1) * 4;     // 0 or 4
    const float* Ap = A + (size_t)(bm + rowL) * DM + colL;
    const float* Bp = B + (size_t)(bn + rowL) * DM + colL;
    const int tr = (tid >> 4) * 8;      // row tile offset
    const int tc = (tid & 15) * 8;      // col tile offset

    for (int k0 = 0; k0 < DM; k0 += 8) {
        float4 a4 = *(const float4*)(Ap + k0);
        float4 b4 = *(const float4*)(Bp + k0);
        __syncthreads();   // previous compute done before overwrite
        As[colL+0][rowL] = a4.x; As[colL+1][rowL] = a4.y;
        As[colL+2][rowL] = a4.z; As[colL+3][rowL] = a4.w;
        Bs[colL+0][rowL] = b4.x; Bs[colL+1][rowL] = b4.y;
        Bs[colL+2][rowL] = b4.z; Bs[colL+3][rowL] = b4.w;
        __syncthreads();
        #pragma unroll
        for (int k = 0; k < 8; k++) {
            float4 a0 = *(const float4*)&As[k][tr];
            float4 a1 = *(const float4*)&As[k][tr + 4];
            F4U2 b0, b1;
            b0.f4 = *(const float4*)&Bs[k][tc];
            b1.f4 = *(const float4*)&Bs[k][tc + 4];
            u64 rb0 = b0.u2[0], rb1 = b0.u2[1], rb2 = b1.u2[0], rb3 = b1.u2[1];
            float ra[8] = {a0.x, a0.y, a0.z, a0.w, a1.x, a1.y, a1.z, a1.w};
            #pragma unroll
            for (int i = 0; i < 8; i++) {
                u64 ai = pack2(ra[i], ra[i]);
                fma2(acc[i][0], ai, rb0);
                fma2(acc[i][1], ai, rb1);
                fma2(acc[i][2], ai, rb2);
                fma2(acc[i][3], ai, rb3);
            }
        }
    }
}

// ============================================================
// QKV projection + RoPE.  z: 0=Q(rope), 1=K(rope), 2=V
// Writes [b,h,s,d] layout for attention.
// ============================================================
__global__ __launch_bounds__(256, 2)
void qkv_kernel(const float* __restrict__ x, const int* __restrict__ posns,
                const float* __restrict__ wq, const float* __restrict__ wk,
                const float* __restrict__ wv)
{
    const int z = blockIdx.z;
    const float* B = (z == 0) ? wq : (z == 1) ? wk : wv;
    u64 acc[8][4] = {};
    gemm128(x, B, acc);

    float* dst = (z == 0) ? g_q : (z == 1) ? g_k : g_v;
    const int tid = threadIdx.x;
    const int bm  = blockIdx.y * 128;
    const int bn  = blockIdx.x * 128;
    const int tr  = (tid >> 4) * 8;
    const int tc  = (tid & 15) * 8;
    const int cn0 = bn + tc;            // 8 consecutive cols, within one head
    const int h   = cn0 >> 6;
    const int d0  = cn0 & 63;

    float inv[4];
    if (z < 2) {
        #pragma unroll
        for (int t2 = 0; t2 < 4; t2++)
            inv[t2] = 1.0f / powf(10000.0f, (float)(d0 + 2*t2) * (1.0f/64.0f));
    }

    #pragma unroll
    for (int i = 0; i < 8; i++) {
        int rm = bm + tr + i;
        int bb = rm >> 11;
        int s  = rm & 2047;
        float2 c0 = unpack2(acc[i][0]);
        float2 c1 = unpack2(acc[i][1]);
        float2 c2 = unpack2(acc[i][2]);
        float2 c3 = unpack2(acc[i][3]);
        float y[8] = {c0.x, c0.y, c1.x, c1.y, c2.x, c2.y, c3.x, c3.y};
        if (z < 2) {
            float fp = (float)posns[s];
            #pragma unroll
            for (int t2 = 0; t2 < 4; t2++) {
                float ang = fp * inv[t2];
                float sn, cs;
                sincosf(ang, &sn, &cs);
                float x0 = y[2*t2], x1 = y[2*t2 + 1];
                y[2*t2]     = x0 * cs - x1 * sn;
                y[2*t2 + 1] = x0 * sn + x1 * cs;
            }
        }
        float* drow = dst + (((size_t)(bb * NH + h) * SEQ + s) * DKK + d0);
        *(float4*)&drow[0] = make_float4(y[0], y[1], y[2], y[3]);
        *(float4*)&drow[4] = make_float4(y[4], y[5], y[6], y[7]);
    }
}

// ============================================================
// Causal flash attention, fp32, 1 thread = 1 query row.
// Block: 128 threads = 128 queries of one (b,h). K/V tiles (64x64) in smem.
// q pre-scaled by 1/sqrt(dk). Online softmax with rare-rescale branch.
// ============================================================
__global__ __launch_bounds__(128)
void attn_kernel()
{
    const int t  = threadIdx.x;
    const int q0 = blockIdx.x * 128;
    const int h  = blockIdx.y;
    const int b  = blockIdx.z;
    const int qi = q0 + t;
    const size_t base = (size_t)(b * NH + h) * SEQ * DKK;

    // load & pre-scale query (packed pairs)
    u64 q2[32];
    {
        const float* Qp = g_q + base + (size_t)qi * DKK;
        #pragma unroll
        for (int i = 0; i < 16; i++) {
            float4 v = *(const float4*)(Qp + i * 4);
            q2[2*i]     = pack2(v.x * 0.125f, v.y * 0.125f);
            q2[2*i + 1] = pack2(v.z * 0.125f, v.w * 0.125f);
        }
    }
    u64 o2[32] = {};
    float mrow = -1e30f;
    float l = 0.0f;

    __shared__ float Ks[64 * 64];
    __shared__ float Vs[64 * 64];

    const int kend = q0 + 128;   // exclusive bound on keys needed by this block
    for (int kt = 0; kt < kend; kt += 64) {
        const float* Kg = g_k + base + (size_t)kt * DKK;
        const float* Vg = g_v + base + (size_t)kt * DKK;
        __syncthreads();
        #pragma unroll
        for (int r = 0; r < 8; r++) {
            int idx = (t + r * 128) * 4;   // float offset 0..4092
            *(float4*)&Ks[idx] = *(const float4*)&Kg[idx];
            *(float4*)&Vs[idx] = *(const float4*)&Vg[idx];
        }
        __syncthreads();

        int jmax = qi - kt + 1;
        if (jmax > 64) jmax = 64;
        for (int j = 0; j < jmax; j++) {
            // s = q . k_j   (4 packed accumulator chains)
            const float4* Kf4 = (const float4*)(Ks + j * 64);
            u64 accs[4] = {0, 0, 0, 0};
            #pragma unroll
            for (int i2 = 0; i2 < 16; i2++) {
                F4U2 kk; kk.f4 = Kf4[i2];
                fma2(accs[(2*i2)     & 3], q2[2*i2],     kk.u2[0]);
                fma2(accs[(2*i2 + 1) & 3], q2[2*i2 + 1], kk.u2[1]);
            }
            float2 fa = unpack2(accs[0]), fb = unpack2(accs[1]);
            float2 fc = unpack2(accs[2]), fd = unpack2(accs[3]);
            float s = ((fa.x + fa.y) + (fb.x + fb.y)) +
                      ((fc.x + fc.y) + (fd.x + fd.y));

            if (s > mrow) {           // rare after warmup
                float r = __expf(mrow - s);
                u64 r2 = pack2(r, r);
                #pragma unroll
                for (int i = 0; i < 32; i++) mul2(o2[i], r2);
                l *= r;
                mrow = s;
            }
            float p = __expf(s - mrow);
            l += p;
            u64 p2 = pack2(p, p);
            const float4* Vf4 = (const float4*)(Vs + j * 64);
            #pragma unroll
            for (int i2 = 0; i2 < 16; i2++) {
                F4U2 vv; vv.f4 = Vf4[i2];
                fma2(o2[2*i2],     p2, vv.u2[0]);
                fma2(o2[2*i2 + 1], p2, vv.u2[1]);
            }
        }
    }

    float invl = 1.0f / l;
    float* dst = g_attn + ((size_t)(b * SEQ + qi) * NH + h) * DKK;
    #pragma unroll
    for (int i = 0; i < 16; i++) {
        float2 a = unpack2(o2[2*i]);
        float2 c = unpack2(o2[2*i + 1]);
        *(float4*)&dst[i * 4] =
            make_float4(a.x * invl, a.y * invl, c.x * invl, c.y * invl);
    }
}

// ============================================================
// Output projection: d_out = g_attn @ w_o^T
// ============================================================
__global__ __launch_bounds__(256, 2)
void out_kernel(const float* __restrict__ wo, float* __restrict__ outp)
{
    u64 acc[8][4] = {};
    gemm128(g_attn, wo, acc);

    const int tid = threadIdx.x;
    const int bm  = blockIdx.y * 128;
    const int cn0 = blockIdx.x * 128 + (tid & 15) * 8;
    const int tr  = (tid >> 4) * 8;
    #pragma unroll
    for (int i = 0; i < 8; i++) {
        int rm = bm + tr + i;
        float2 c0 = unpack2(acc[i][0]);
        float2 c1 = unpack2(acc[i][1]);
        float2 c2 = unpack2(acc[i][2]);
        float2 c3 = unpack2(acc[i][3]);
        float* drow = outp + (size_t)rm * DM + cn0;
        *(float4*)&drow[0] = make_float4(c0.x, c0.y, c1.x, c1.y);
        *(float4*)&drow[4] = make_float4(c2.x, c2.y, c3.x, c3.y);
    }
}

extern "C" void kernel_launch(void* const* d_in, const int* in_sizes, int n_in,
                              void* d_out, int out_size)
{
    (void)in_sizes; (void)n_in; (void)out_size;
    const float* x    = (const float*)d_in[0];
    const int*   pos  = (const int*)  d_in[1];
    const float* wq   = (const float*)d_in[2];
    const float* wk   = (const float*)d_in[3];
    const float* wv   = (const float*)d_in[4];
    const float* wo   = (const float*)d_in[5];
    float*       outp = (float*)d_out;

    dim3 g1(DM / 128, MT / 128, 3);          // (8, 32, 3)
    qkv_kernel<<<g1, 256>>>(x, pos, wq, wk, wv);

    dim3 g2(SEQ / 128, NH, BATCH);           // (16, 16, 2)
    attn_kernel<<<g2, 128>>>();

    dim3 g3(DM / 128, MT / 128, 1);          // (8, 32)
    out_kernel<<<g3, 256>>>(wo, outp);
}

// round 9
// speedup vs baseline: 1.0218x; 1.0071x over previous
#include <cuda_runtime.h>
#include <math.h>

typedef unsigned long long u64;

#define SEQ   2048
#define DM    1024
#define NH    16
#define DKK   64
#define BATCH 2
#define MT    (BATCH*SEQ)   // 4096 rows

// Scratch (device globals: allocation-free rule)
__device__ float g_q[BATCH*NH*SEQ*DKK];     // [b,h,s,d]
__device__ float g_k[BATCH*NH*SEQ*DKK];     // [b,h,s,d]
__device__ float g_v[BATCH*NH*SEQ*DKK];     // [b,h,s,d]
__device__ float g_attn[MT*DM];             // [m, h*64+d] row-major

// ---- packed fp32x2 helpers (B300 double-rate fp32) ----
__device__ __forceinline__ u64 pack2(float x, float y) {
    u64 r; asm("mov.b64 %0, {%1, %2};" : "=l"(r) : "f"(x), "f"(y)); return r;
}
__device__ __forceinline__ float2 unpack2(u64 v) {
    float2 f; asm("mov.b64 {%0, %1}, %2;" : "=f"(f.x), "=f"(f.y) : "l"(v)); return f;
}
__device__ __forceinline__ void fma2(u64& d, u64 a, u64 b) {
    asm("fma.rn.f32x2 %0, %1, %2, %0;" : "+l"(d) : "l"(a), "l"(b));
}
__device__ __forceinline__ void mul2(u64& d, u64 a) {
    asm("mul.rn.f32x2 %0, %0, %1;" : "+l"(d) : "l"(a));
}

union F4U2 { float4 f4; u64 u2[2]; };

// ============================================================
// 128x128x8 SGEMM tile, C[m,n] = sum_k A[m,k]*B[n,k]
// 256 threads, 8x8 per thread, inner products via fma.rn.f32x2
// ============================================================
__device__ __forceinline__ void gemm128(const float* __restrict__ A,
                                        const float* __restrict__ B,
                                        u64 acc[8][4])
{
    __shared__ float As[8][128];
    __shared__ float Bs[8][128];
    const int tid  = threadIdx.x;
    const int bm   = blockIdx.y * 128;
    const int bn   = blockIdx.x * 128;
    const int rowL = tid >> 1;          // 0..127
    const int colL = (tid & 1) * 4;     // 0 or 4
    const float* Ap = A + (size_t)(bm + rowL) * DM + colL;
    const float* Bp = B + (size_t)(bn + rowL) * DM + colL;
    const int tr = (tid >> 4) * 8;      // row tile offset
    const int tc = (tid & 15) * 8;      // col tile offset

    for (int k0 = 0; k0 < DM; k0 += 8) {
        float4 a4 = *(const float4*)(Ap + k0);
        float4 b4 = *(const float4*)(Bp + k0);
        __syncthreads();   // previous compute done before overwrite
        As[colL+0][rowL] = a4.x; As[colL+1][rowL] = a4.y;
        As[colL+2][rowL] = a4.z; As[colL+3][rowL] = a4.w;
        Bs[colL+0][rowL] = b4.x; Bs[colL+1][rowL] = b4.y;
        Bs[colL+2][rowL] = b4.z; Bs[colL+3][rowL] = b4.w;
        __syncthreads();
        #pragma unroll
        for (int k = 0; k < 8; k++) {
            float4 a0 = *(const float4*)&As[k][tr];
            float4 a1 = *(const float4*)&As[k][tr + 4];
            F4U2 b0, b1;
            b0.f4 = *(const float4*)&Bs[k][tc];
            b1.f4 = *(const float4*)&Bs[k][tc + 4];
            u64 rb0 = b0.u2[0], rb1 = b0.u2[1], rb2 = b1.u2[0], rb3 = b1.u2[1];
            float ra[8] = {a0.x, a0.y, a0.z, a0.w, a1.x, a1.y, a1.z, a1.w};
            #pragma unroll
            for (int i = 0; i < 8; i++) {
                u64 ai = pack2(ra[i], ra[i]);
                fma2(acc[i][0], ai, rb0);
                fma2(acc[i][1], ai, rb1);
                fma2(acc[i][2], ai, rb2);
                fma2(acc[i][3], ai, rb3);
            }
        }
    }
}

// ============================================================
// QKV projection + RoPE.  z: 0=Q(rope), 1=K(rope), 2=V
// Writes [b,h,s,d] layout for attention.
// ============================================================
__global__ __launch_bounds__(256, 2)
void qkv_kernel(const float* __restrict__ x, const int* __restrict__ posns,
                const float* __restrict__ wq, const float* __restrict__ wk,
                const float* __restrict__ wv)
{
    const int z = blockIdx.z;
    const float* B = (z == 0) ? wq : (z == 1) ? wk : wv;
    u64 acc[8][4] = {};
    gemm128(x, B, acc);

    float* dst = (z == 0) ? g_q : (z == 1) ? g_k : g_v;
    const int tid = threadIdx.x;
    const int bm  = blockIdx.y * 128;
    const int bn  = blockIdx.x * 128;
    const int tr  = (tid >> 4) * 8;
    const int tc  = (tid & 15) * 8;
    const int cn0 = bn + tc;            // 8 consecutive cols, within one head
    const int h   = cn0 >> 6;
    const int d0  = cn0 & 63;

    float inv[4];
    if (z < 2) {
        #pragma unroll
        for (int t2 = 0; t2 < 4; t2++)
            inv[t2] = 1.0f / powf(10000.0f, (float)(d0 + 2*t2) * (1.0f/64.0f));
    }

    #pragma unroll
    for (int i = 0; i < 8; i++) {
        int rm = bm + tr + i;
        int bb = rm >> 11;
        int s  = rm & 2047;
        float2 c0 = unpack2(acc[i][0]);
        float2 c1 = unpack2(acc[i][1]);
        float2 c2 = unpack2(acc[i][2]);
        float2 c3 = unpack2(acc[i][3]);
        float y[8] = {c0.x, c0.y, c1.x, c1.y, c2.x, c2.y, c3.x, c3.y};
        if (z < 2) {
            float fp = (float)posns[s];
            #pragma unroll
            for (int t2 = 0; t2 < 4; t2++) {
                float ang = fp * inv[t2];
                float sn, cs;
                sincosf(ang, &sn, &cs);
                float x0 = y[2*t2], x1 = y[2*t2 + 1];
                y[2*t2]     = x0 * cs - x1 * sn;
                y[2*t2 + 1] = x0 * sn + x1 * cs;
            }
        }
        float* drow = dst + (((size_t)(bb * NH + h) * SEQ + s) * DKK + d0);
        *(float4*)&drow[0] = make_float4(y[0], y[1], y[2], y[3]);
        *(float4*)&drow[4] = make_float4(y[4], y[5], y[6], y[7]);
    }
}

// ============================================================
// Causal flash attention, fp32, 1 thread = 1 query row.
// Block: 128 threads = 128 queries of one (b,h). K/V tiles (64x64) in smem.
// q pre-scaled by 1/sqrt(dk). Online softmax with rare-rescale branch.
// ============================================================
__global__ __launch_bounds__(128)
void attn_kernel()
{
    const int t  = threadIdx.x;
    const int q0 = blockIdx.x * 128;
    const int h  = blockIdx.y;
    const int b  = blockIdx.z;
    const int qi = q0 + t;
    const size_t base = (size_t)(b * NH + h) * SEQ * DKK;

    // load & pre-scale query (packed pairs)
    u64 q2[32];
    {
        const float* Qp = g_q + base + (size_t)qi * DKK;
        #pragma unroll
        for (int i = 0; i < 16; i++) {
            float4 v = *(const float4*)(Qp + i * 4);
            q2[2*i]     = pack2(v.x * 0.125f, v.y * 0.125f);
            q2[2*i + 1] = pack2(v.z * 0.125f, v.w * 0.125f);
        }
    }
    u64 o2[32] = {};
    float mrow = -1e30f;
    float l = 0.0f;

    __shared__ float Ks[64 * 64];
    __shared__ float Vs[64 * 64];

    const int kend = q0 + 128;   // exclusive bound on keys needed by this block
    for (int kt = 0; kt < kend; kt += 64) {
        const float* Kg = g_k + base + (size_t)kt * DKK;
        const float* Vg = g_v + base + (size_t)kt * DKK;
        __syncthreads();
        #pragma unroll
        for (int r = 0; r < 8; r++) {
            int idx = (t + r * 128) * 4;   // float offset 0..4092
            *(float4*)&Ks[idx] = *(const float4*)&Kg[idx];
            *(float4*)&Vs[idx] = *(const float4*)&Vg[idx];
        }
        __syncthreads();

        int jmax = qi - kt + 1;
        if (jmax > 64) jmax = 64;
        for (int j = 0; j < jmax; j++) {
            // s = q . k_j   (4 packed accumulator chains)
            const float4* Kf4 = (const float4*)(Ks + j * 64);
            u64 accs[4] = {0, 0, 0, 0};
            #pragma unroll
            for (int i2 = 0; i2 < 16; i2++) {
                F4U2 kk; kk.f4 = Kf4[i2];
                fma2(accs[(2*i2)     & 3], q2[2*i2],     kk.u2[0]);
                fma2(accs[(2*i2 + 1) & 3], q2[2*i2 + 1], kk.u2[1]);
            }
            float2 fa = unpack2(accs[0]), fb = unpack2(accs[1]);
            float2 fc = unpack2(accs[2]), fd = unpack2(accs[3]);
            float s = ((fa.x + fa.y) + (fb.x + fb.y)) +
                      ((fc.x + fc.y) + (fd.x + fd.y));

            if (s > mrow) {           // rare after warmup
                float r = __expf(mrow - s);
                u64 r2 = pack2(r, r);
                #pragma unroll
                for (int i = 0; i < 32; i++) mul2(o2[i], r2);
                l *= r;
                mrow = s;
            }
            float p = __expf(s - mrow);
            l += p;
            u64 p2 = pack2(p, p);
            const float4* Vf4 = (const float4*)(Vs + j * 64);
            #pragma unroll
            for (int i2 = 0; i2 < 16; i2++) {
                F4U2 vv; vv.f4 = Vf4[i2];
                fma2(o2[2*i2],     p2, vv.u2[0]);
                fma2(o2[2*i2 + 1], p2, vv.u2[1]);
            }
        }
    }

    float invl = 1.0f / l;
    float* dst = g_attn + ((size_t)(b * SEQ + qi) * NH + h) * DKK;
    #pragma unroll
    for (int i = 0; i < 16; i++) {
        float2 a = unpack2(o2[2*i]);
        float2 c = unpack2(o2[2*i + 1]);
        *(float4*)&dst[i * 4] =
            make_float4(a.x * invl, a.y * invl, c.x * invl, c.y * invl);
    }
}

// ============================================================
// Output projection: d_out = g_attn @ w_o^T
// ============================================================
__global__ __launch_bounds__(256, 2)
void out_kernel(const float* __restrict__ wo, float* __restrict__ outp)
{
    u64 acc[8][4] = {};
    gemm128(g_attn, wo, acc);

    const int tid = threadIdx.x;
    const int bm  = blockIdx.y * 128;
    const int cn0 = blockIdx.x * 128 + (tid & 15) * 8;
    const int tr  = (tid >> 4) * 8;
    #pragma unroll
    for (int i = 0; i < 8; i++) {
        int rm = bm + tr + i;
        float2 c0 = unpack2(acc[i][0]);
        float2 c1 = unpack2(acc[i][1]);
        float2 c2 = unpack2(acc[i][2]);
        float2 c3 = unpack2(acc[i][3]);
        float* drow = outp + (size_t)rm * DM + cn0;
        *(float4*)&drow[0] = make_float4(c0.x, c0.y, c1.x, c1.y);
        *(float4*)&drow[4] = make_float4(c2.x, c2.y, c3.x, c3.y);
    }
}

extern "C" void kernel_launch(void* const* d_in, const int* in_sizes, int n_in,
                              void* d_out, int out_size)
{
    (void)in_sizes; (void)n_in; (void)out_size;
    const float* x    = (const float*)d_in[0];
    const int*   pos  = (const int*)  d_in[1];
    const float* wq   = (const float*)d_in[2];
    const float* wk   = (const float*)d_in[3];
    const float* wv   = (const float*)d_in[4];
    const float* wo   = (const float*)d_in[5];
    float*       outp = (float*)d_out;

    dim3 g1(DM / 128, MT / 128, 3);          // (8, 32, 3)
    qkv_kernel<<<g1, 256>>>(x, pos, wq, wk, wv);

    dim3 g2(SEQ / 128, NH, BATCH);           // (16, 16, 2)
    attn_kernel<<<g2, 128>>>();

    dim3 g3(DM / 128, MT / 128, 1);          // (8, 32)
    out_kernel<<<g3, 256>>>(wo, outp);
}